// round 7
// baseline (speedup 1.0000x reference)
#include <cuda_runtime.h>
#include <cuda_fp16.h>
#include <cstdint>

// ------------------------- problem constants -------------------------
#define CC 256
#define LL 8192
#define BB 32
#define TL 64            // positions per CTA
#define KC 32            // K chunk
#define NCHUNK 8
#define NSTAGE 3

// ------------------------- smem layout (bytes) -----------------------
#define WOFF(s)  ((s) * 16384)            // W fp16 frag-order: 3 x 16KB
#define XOFF(s)  (49152 + (s) * 8704)     // x raw fp32: 32 k-rows x 68 words
#define XSTR     68                       // words per x row (bank-perfect)
#define SBIAS    75264                    // 256 floats
#define SQBUF    76288                    // 4 x 64 floats
#define SCALE    77312                    // 64 floats
#define SMEM_BYTES 77568
// epilogue: out tile [64 pos][268 words] at offset 0 (reuses stage region)
#define OSTR     268

// ------------------------- device scratch ----------------------------
// W' fp16 pairs in exact A-fragment order:
// idx = (((kc*2+ks)*16 + mb)*32 + lane)*4 + reg   (each u32 = 2 fp16, k-pair)
__device__ __align__(16) unsigned g_Wf[CC * CC / 2];
__device__ float g_bias[CC];

// ------------------------- helpers -----------------------------------
__device__ __forceinline__ uint32_t smem_u32(const void* p) {
    uint32_t a;
    asm("{ .reg .u64 t; cvta.to.shared.u64 t, %1; cvt.u32.u64 %0, t; }"
        : "=r"(a) : "l"(p));
    return a;
}
__device__ __forceinline__ uint32_t pkh2(float a, float b) {
    __half2 h = __floats2half2_rn(a, b);
    return *reinterpret_cast<uint32_t*>(&h);
}
__device__ __forceinline__ void cp16(uint32_t dst, const void* src) {
    asm volatile("cp.async.cg.shared.global [%0], [%1], 16;\n" :: "r"(dst), "l"(src));
}
#define CP_COMMIT() asm volatile("cp.async.commit_group;\n" ::: "memory")
#define CP_WAIT2()  asm volatile("cp.async.wait_group 2;\n" ::: "memory")

__device__ __forceinline__ void mma_f16(float* d, const uint32_t* a, const uint32_t* b) {
    asm volatile(
        "mma.sync.aligned.m16n8k16.row.col.f32.f16.f16.f32 "
        "{%0,%1,%2,%3}, {%4,%5,%6,%7}, {%8,%9}, {%0,%1,%2,%3};"
        : "+f"(d[0]), "+f"(d[1]), "+f"(d[2]), "+f"(d[3])
        : "r"(a[0]), "r"(a[1]), "r"(a[2]), "r"(a[3]), "r"(b[0]), "r"(b[1]));
}

// ------------------------- prep kernel -------------------------------
// Fold BN into W, convert fp16, emit A-fragment-order image (k-pairs packed).
__global__ void fold_kernel(const float* __restrict__ W, const float* __restrict__ b,
                            const float* __restrict__ gamma, const float* __restrict__ beta,
                            const float* __restrict__ mean, const float* __restrict__ var) {
    int o = blockIdx.x;
    int j = threadIdx.x;          // c pair: c = 2j, 2j+1
    float inv = gamma[o] * rsqrtf(var[o] + 1e-5f);
    int c = 2 * j;
    float w0 = W[o * CC + c] * inv;
    float w1 = W[o * CC + c + 1] * inv;
    int kc = c >> 5;              // 32-chunk
    int ks = (c >> 4) & 1;        // k16 step within chunk
    int kl = c & 15;              // k within 16 (even)
    int mb = o >> 4;
    int lane = (o & 7) * 4 + ((kl >> 1) & 3);
    int reg  = ((o >> 3) & 1) + 2 * (kl >> 3);
    g_Wf[(((kc * 2 + ks) * 16 + mb) * 32 + lane) * 4 + reg] = pkh2(w0, w1);
    if (j == 0) g_bias[o] = b[o] * inv + beta[o] - mean[o] * inv;
}

// ------------------------- main kernel -------------------------------
// 256 threads, 8 warps: wm 0..3 (64 oc), wn 0..1 (32 pos). 2 CTAs/SM.
// Tile 256 oc x 64 pos; K in 8 chunks of 32; W and x both cp.async at
// distance 2 (3-ring). B-frags: raw fp32 LDS + f16x2 pack.
extern "C" __global__ void __launch_bounds__(256, 2)
caps_kernel(const float* __restrict__ x, float* __restrict__ out) {
    extern __shared__ char smem[];
    const uint32_t sbu = smem_u32(smem);
    const int t    = threadIdx.x;
    const int lane = t & 31;
    const int wid  = t >> 5;
    const int wm   = wid & 3;
    const int wn   = wid >> 2;
    const int m0   = wm * 64;
    const int bb   = blockIdx.y;
    const int l0   = blockIdx.x * TL;

    ((float*)(smem + SBIAS))[t] = g_bias[t];

    const float* xg = x + (size_t)bb * CC * LL + l0;

    float acc[4][4][4];
    #pragma unroll
    for (int i = 0; i < 4; i++)
        #pragma unroll
        for (int j = 0; j < 4; j++)
            #pragma unroll
            for (int q = 0; q < 4; q++) acc[i][j][q] = 0.0f;

    // ---- one K-chunk: W frag image + raw fp32 x, single commit group ----
    const int xr  = t >> 3;       // x row (k within chunk) 0..31
    const int xc  = t & 7;        // 16B segment pair base
    auto issue = [&](int kc, int st) {
        uint32_t dW = sbu + WOFF(st);
        const char* sW = (const char*)(g_Wf + kc * 4096);
        #pragma unroll
        for (int i = 0; i < 4; i++) {
            int e = t + i * 256;
            cp16(dW + e * 16, sW + e * 16);
        }
        uint32_t dX = sbu + XOFF(st) + (uint32_t)(xr * XSTR) * 4;
        const float* sX = xg + (size_t)(kc * KC + xr) * LL;
        cp16(dX + (xc * 2) * 16,     sX + xc * 8);
        cp16(dX + (xc * 2 + 1) * 16, sX + xc * 8 + 4);
        CP_COMMIT();
    };

    // ---- mma over one resident chunk: 2 k16-steps ----
    auto do_mma = [&](int st) {
        const char* Wb  = smem + WOFF(st);
        const float* Xw = (const float*)(smem + XOFF(st))
                          + (lane & 3) * 2 * XSTR + wn * 32 + (lane >> 2);
        #pragma unroll
        for (int ks = 0; ks < 2; ks++) {
            uint32_t af[4][4], bf[4][2];
            #pragma unroll
            for (int i = 0; i < 4; i++) {
                uint4 v = *(const uint4*)(Wb + ((ks * 16 + wm * 4 + i) * 32 + lane) * 16);
                af[i][0] = v.x; af[i][1] = v.y; af[i][2] = v.z; af[i][3] = v.w;
            }
            const float* xb = Xw + ks * 16 * XSTR;
            #pragma unroll
            for (int j = 0; j < 4; j++) {
                const float* p = xb + j * 8;
                bf[j][0] = pkh2(p[0],        p[XSTR]);
                bf[j][1] = pkh2(p[8 * XSTR], p[9 * XSTR]);
            }
            #pragma unroll
            for (int i = 0; i < 4; i++)
                #pragma unroll
                for (int j = 0; j < 4; j++)
                    mma_f16(acc[i][j], af[i], bf[j]);
        }
    };

    // ---- pipeline: distance-2, 3-ring, 2 barriers per chunk ----
    issue(0, 0);
    issue(1, 1);

    for (int k = 0; k < NCHUNK; k++) {
        __syncthreads();                   // all warps done mma(k-1): ring slot free
        if (k + 2 < NCHUNK) issue(k + 2, (k + 2) % NSTAGE);
        else CP_COMMIT();                  // keep group accounting uniform
        CP_WAIT2();                        // W(k), x(k) arrived (own ops)
        __syncthreads();                   // everyone's cp.async visible
        do_mma(k % NSTAGE);
    }

    // ---- epilogue: bias + squash, smem-staged coalesced store ----
    const float* sbias = (const float*)(smem + SBIAS);
    const int gid = lane >> 2;
    const int qid = lane & 3;
    const int n0  = wn * 32;

    float sqA[4], sqB[4];
    #pragma unroll
    for (int j = 0; j < 4; j++) { sqA[j] = 0.0f; sqB[j] = 0.0f; }

    #pragma unroll
    for (int i = 0; i < 4; i++) {
        int r0 = m0 + i * 16 + gid;
        float b0 = sbias[r0], b1 = sbias[r0 + 8];
        #pragma unroll
        for (int j = 0; j < 4; j++) {
            float y0 = acc[i][j][0] + b0;
            float y1 = acc[i][j][1] + b0;
            float y2 = acc[i][j][2] + b1;
            float y3 = acc[i][j][3] + b1;
            acc[i][j][0] = y0; acc[i][j][1] = y1;
            acc[i][j][2] = y2; acc[i][j][3] = y3;
            sqA[j] += y0 * y0 + y2 * y2;
            sqB[j] += y1 * y1 + y3 * y3;
        }
    }
    #pragma unroll
    for (int j = 0; j < 4; j++) {
        #pragma unroll
        for (int m = 4; m < 32; m <<= 1) {
            sqA[j] += __shfl_xor_sync(0xffffffffu, sqA[j], m);
            sqB[j] += __shfl_xor_sync(0xffffffffu, sqB[j], m);
        }
    }

    __syncthreads();                       // stage buffers now reusable as OUT
    float* ot = (float*)smem;              // [64 pos][OSTR words]
    #pragma unroll
    for (int i = 0; i < 4; i++) {
        int r0 = m0 + i * 16 + gid;
        #pragma unroll
        for (int j = 0; j < 4; j++) {
            int c0 = n0 + j * 8 + qid * 2;
            ot[c0 * OSTR + r0]           = acc[i][j][0];
            ot[(c0 + 1) * OSTR + r0]     = acc[i][j][1];
            ot[c0 * OSTR + r0 + 8]       = acc[i][j][2];
            ot[(c0 + 1) * OSTR + r0 + 8] = acc[i][j][3];
        }
    }
    float* sqb = (float*)(smem + SQBUF);
    if (lane < 4) {
        #pragma unroll
        for (int j = 0; j < 4; j++) {
            int col = n0 + j * 8 + lane * 2;
            sqb[wm * 64 + col]     = sqA[j];
            sqb[wm * 64 + col + 1] = sqB[j];
        }
    }
    __syncthreads();
    if (t < 64) {
        float s = sqb[t] + sqb[64 + t] + sqb[128 + t] + sqb[192 + t];
        float n = sqrtf(s);
        ((float*)(smem + SCALE))[t] = s / ((1.0f + s) * (n + 1e-8f));
    }
    __syncthreads();

    const float* scl = (const float*)(smem + SCALE);
    float* og = out + ((size_t)bb * LL + l0) * CC;
    #pragma unroll
    for (int it = 0; it < 16; it++) {
        int f   = it * 256 + t;
        int pos = f >> 6;
        int c4  = f & 63;
        float4 v = *(const float4*)(ot + pos * OSTR + c4 * 4);
        float s = scl[pos];
        v.x *= s; v.y *= s; v.z *= s; v.w *= s;
        *(float4*)(og + (size_t)pos * CC + c4 * 4) = v;
    }
}

// ------------------------- launch ------------------------------------
extern "C" void kernel_launch(void* const* d_in, const int* in_sizes, int n_in,
                              void* d_out, int out_size) {
    const float* x     = (const float*)d_in[0];
    const float* W     = (const float*)d_in[1];
    const float* b     = (const float*)d_in[2];
    const float* gamma = (const float*)d_in[3];
    const float* beta  = (const float*)d_in[4];
    const float* mean  = (const float*)d_in[5];
    const float* var   = (const float*)d_in[6];
    float* out = (float*)d_out;

    fold_kernel<<<CC, 128>>>(W, b, gamma, beta, mean, var);

    cudaFuncSetAttribute(caps_kernel,
                         cudaFuncAttributeMaxDynamicSharedMemorySize, SMEM_BYTES);
    dim3 grid(LL / TL, BB);
    caps_kernel<<<grid, 256, SMEM_BYTES>>>(x, out);
}

// round 8
// speedup vs baseline: 1.0806x; 1.0806x over previous
#include <cuda_runtime.h>
#include <cuda_fp16.h>
#include <cstdint>

// ------------------------- problem constants -------------------------
#define CC 256
#define LL 8192
#define BB 32
#define TL 64            // positions per CTA
#define KC 32            // K chunk
#define NCHUNK 8
#define NSTAGE 4

// ------------------------- smem layout (bytes) -----------------------
#define WOFF(s)  ((s) * 16384)            // W fp16 frag-order: 4 x 16KB
#define XOFF(s)  (65536 + (s) * 4096)     // x fp16: 32 k-rows x 128B (xor-swizzled)
#define SBIAS    81920                    // 256 floats
#define SQBUF    82944                    // 4 x 64 floats
#define SCALE    84224                    // 64 floats
#define SMEM_BYTES 84480
// epilogue reuse: out tile [64 pos][268 words] at offset 0
#define OSTR     268

// ------------------------- device scratch ----------------------------
// W' fp16 pairs in exact A-fragment order:
// idx = (((kc*2+ks)*16 + mb)*32 + lane)*4 + reg   (each u32 = 2 fp16, k-pair)
__device__ __align__(16) unsigned g_Wf[CC * CC / 2];
__device__ float g_bias[CC];

// ------------------------- helpers -----------------------------------
__device__ __forceinline__ uint32_t smem_u32(const void* p) {
    uint32_t a;
    asm("{ .reg .u64 t; cvta.to.shared.u64 t, %1; cvt.u32.u64 %0, t; }"
        : "=r"(a) : "l"(p));
    return a;
}
__device__ __forceinline__ uint32_t pkh2(float a, float b) {
    __half2 h = __floats2half2_rn(a, b);
    return *reinterpret_cast<uint32_t*>(&h);
}
__device__ __forceinline__ void cp16(uint32_t dst, const void* src) {
    asm volatile("cp.async.cg.shared.global [%0], [%1], 16;\n" :: "r"(dst), "l"(src));
}
#define CP_COMMIT() asm volatile("cp.async.commit_group;\n" ::: "memory")
#define CP_WAIT2()  asm volatile("cp.async.wait_group 2;\n" ::: "memory")

__device__ __forceinline__ void ldsm_x2t(uint32_t* r, uint32_t addr) {
    asm volatile("ldmatrix.sync.aligned.m8n8.x2.trans.shared.b16 {%0,%1}, [%2];"
                 : "=r"(r[0]), "=r"(r[1]) : "r"(addr));
}
__device__ __forceinline__ void mma_f16(float* d, const uint32_t* a, const uint32_t* b) {
    asm volatile(
        "mma.sync.aligned.m16n8k16.row.col.f32.f16.f16.f32 "
        "{%0,%1,%2,%3}, {%4,%5,%6,%7}, {%8,%9}, {%0,%1,%2,%3};"
        : "+f"(d[0]), "+f"(d[1]), "+f"(d[2]), "+f"(d[3])
        : "r"(a[0]), "r"(a[1]), "r"(a[2]), "r"(a[3]), "r"(b[0]), "r"(b[1]));
}

// ------------------------- prep kernel -------------------------------
// Fold BN into W, convert fp16, emit A-fragment-order image (k-pairs packed).
__global__ void fold_kernel(const float* __restrict__ W, const float* __restrict__ b,
                            const float* __restrict__ gamma, const float* __restrict__ beta,
                            const float* __restrict__ mean, const float* __restrict__ var) {
    int o = blockIdx.x;
    int j = threadIdx.x;          // c pair: c = 2j, 2j+1
    float inv = gamma[o] * rsqrtf(var[o] + 1e-5f);
    int c = 2 * j;
    float w0 = W[o * CC + c] * inv;
    float w1 = W[o * CC + c + 1] * inv;
    int kc = c >> 5;              // 32-chunk
    int ks = (c >> 4) & 1;        // k16 step within chunk
    int kl = c & 15;              // k within 16 (even)
    int mb = o >> 4;
    int lane = (o & 7) * 4 + ((kl >> 1) & 3);
    int reg  = ((o >> 3) & 1) + 2 * (kl >> 3);
    g_Wf[(((kc * 2 + ks) * 16 + mb) * 32 + lane) * 4 + reg] = pkh2(w0, w1);
    if (j == 0) g_bias[o] = b[o] * inv + beta[o] - mean[o] * inv;
}

// ------------------------- main kernel -------------------------------
// 256 threads, 8 warps: wm 0..3 (64 oc), wn 0..1 (32 pos). 2 CTAs/SM.
// Tile 256 oc x 64 pos; K in 8 chunks of 32; 4-stage ring, distance-2,
// ONE barrier per chunk.
extern "C" __global__ void __launch_bounds__(256, 2)
caps_kernel(const float* __restrict__ x, float* __restrict__ out) {
    extern __shared__ char smem[];
    const uint32_t sbu = smem_u32(smem);
    const int t    = threadIdx.x;
    const int lane = t & 31;
    const int wid  = t >> 5;
    const int wm   = wid & 3;
    const int wn   = wid >> 2;
    const int m0   = wm * 64;
    const int bb   = blockIdx.y;
    const int l0   = blockIdx.x * TL;

    ((float*)(smem + SBIAS))[t] = g_bias[t];

    const float* xg = x + (size_t)bb * CC * LL + l0;

    float acc[4][4][4];
    #pragma unroll
    for (int i = 0; i < 4; i++)
        #pragma unroll
        for (int j = 0; j < 4; j++)
            #pragma unroll
            for (int q = 0; q < 4; q++) acc[i][j][q] = 0.0f;

    // ---- W chunk via cp.async (identity copy of fp16 frag image) ----
    auto issueW = [&](int kc, int st) {
        uint32_t d = sbu + WOFF(st);
        const char* s = (const char*)(g_Wf + kc * 4096);
        #pragma unroll
        for (int i = 0; i < 4; i++) {
            int e = t + i * 256;
            cp16(d + e * 16, s + e * 16);
        }
        CP_COMMIT();
    };

    // ---- x: LDG prefetch (regs), then cvt+STS later ----
    const int xk = t >> 3;      // k row 0..31
    const int xp = t & 7;       // 8-pos group
    const uint32_t xsts = (uint32_t)(xk * 128 + ((xp ^ (xk & 7)) << 4));
    float4 xa, xb2;
    auto ldg_x = [&](int kc) {
        const float* s = xg + (size_t)(kc * KC + xk) * LL + xp * 8;
        xa  = __ldg((const float4*)s);
        xb2 = __ldg((const float4*)(s + 4));
    };
    auto stage_x = [&](int st) {
        uint4 u;
        u.x = pkh2(xa.x, xa.y);   u.y = pkh2(xa.z, xa.w);
        u.z = pkh2(xb2.x, xb2.y); u.w = pkh2(xb2.z, xb2.w);
        *(uint4*)(smem + XOFF(st) + xsts) = u;
    };

    // ---- mma over one resident chunk: 2 k16-steps ----
    auto do_mma = [&](int st) {
        const char* Wb = smem + WOFF(st);
        const uint32_t Xb = sbu + XOFF(st);
        #pragma unroll
        for (int ks = 0; ks < 2; ks++) {
            uint32_t af[4][4], bf[4][2];
            #pragma unroll
            for (int i = 0; i < 4; i++) {
                uint4 v = *(const uint4*)(Wb + ((ks * 16 + wm * 4 + i) * 32 + lane) * 16);
                af[i][0] = v.x; af[i][1] = v.y; af[i][2] = v.z; af[i][3] = v.w;
            }
            #pragma unroll
            for (int j = 0; j < 4; j++)
                ldsm_x2t(bf[j], Xb + (uint32_t)((ks * 16 + (lane & 15)) * 128
                                   + (((wn * 4 + j) ^ (lane & 7)) << 4)));
            #pragma unroll
            for (int i = 0; i < 4; i++)
                #pragma unroll
                for (int j = 0; j < 4; j++)
                    mma_f16(acc[i][j], af[i], bf[j]);
        }
    };

    // ---- 4-ring pipeline, distance 2, ONE barrier per chunk ----
    // Safety: writers of slot (k+2)%4 never collide with readers of slots
    // k%4 / (k+3)%4 (all distinct mod 4); the single barrier provides both
    // cp.async/STS visibility for chunk k and rate-limits warp skew to < 1 chunk.
    issueW(0, 0); ldg_x(0); stage_x(0);
    issueW(1, 1); ldg_x(1); stage_x(1);

    for (int k = 0; k < NCHUNK; k++) {
        if (k + 2 < NCHUNK) {
            issueW(k + 2, (k + 2) % NSTAGE);
            ldg_x(k + 2);
        } else {
            CP_COMMIT();                   // uniform group accounting
        }
        CP_WAIT2();                        // W(k) arrived (own ops)
        __syncthreads();                   // all writes for chunk k visible
        do_mma(k % NSTAGE);
        if (k + 2 < NCHUNK) stage_x((k + 2) % NSTAGE);
    }

    // ---- epilogue: bias + squash, smem-staged coalesced store ----
    const float* sbias = (const float*)(smem + SBIAS);
    const int gid = lane >> 2;
    const int qid = lane & 3;
    const int n0  = wn * 32;

    float sqA[4], sqB[4];
    #pragma unroll
    for (int j = 0; j < 4; j++) { sqA[j] = 0.0f; sqB[j] = 0.0f; }

    #pragma unroll
    for (int i = 0; i < 4; i++) {
        int r0 = m0 + i * 16 + gid;
        float b0 = sbias[r0], b1 = sbias[r0 + 8];
        #pragma unroll
        for (int j = 0; j < 4; j++) {
            float y0 = acc[i][j][0] + b0;
            float y1 = acc[i][j][1] + b0;
            float y2 = acc[i][j][2] + b1;
            float y3 = acc[i][j][3] + b1;
            acc[i][j][0] = y0; acc[i][j][1] = y1;
            acc[i][j][2] = y2; acc[i][j][3] = y3;
            sqA[j] += y0 * y0 + y2 * y2;
            sqB[j] += y1 * y1 + y3 * y3;
        }
    }
    #pragma unroll
    for (int j = 0; j < 4; j++) {
        #pragma unroll
        for (int m = 4; m < 32; m <<= 1) {
            sqA[j] += __shfl_xor_sync(0xffffffffu, sqA[j], m);
            sqB[j] += __shfl_xor_sync(0xffffffffu, sqB[j], m);
        }
    }

    __syncthreads();                       // stage buffers reusable as OUT tile
    float* ot = (float*)smem;              // [64 pos][OSTR words]
    #pragma unroll
    for (int i = 0; i < 4; i++) {
        int r0 = m0 + i * 16 + gid;
        #pragma unroll
        for (int j = 0; j < 4; j++) {
            int c0 = n0 + j * 8 + qid * 2;
            ot[c0 * OSTR + r0]           = acc[i][j][0];
            ot[(c0 + 1) * OSTR + r0]     = acc[i][j][1];
            ot[c0 * OSTR + r0 + 8]       = acc[i][j][2];
            ot[(c0 + 1) * OSTR + r0 + 8] = acc[i][j][3];
        }
    }
    float* sqb = (float*)(smem + SQBUF);
    if (lane < 4) {
        #pragma unroll
        for (int j = 0; j < 4; j++) {
            int col = n0 + j * 8 + lane * 2;
            sqb[wm * 64 + col]     = sqA[j];
            sqb[wm * 64 + col + 1] = sqB[j];
        }
    }
    __syncthreads();
    if (t < 64) {
        float s = sqb[t] + sqb[64 + t] + sqb[128 + t] + sqb[192 + t];
        float n = sqrtf(s);
        ((float*)(smem + SCALE))[t] = s / ((1.0f + s) * (n + 1e-8f));
    }
    __syncthreads();

    const float* scl = (const float*)(smem + SCALE);
    float* og = out + ((size_t)bb * LL + l0) * CC;
    #pragma unroll
    for (int it = 0; it < 16; it++) {
        int f   = it * 256 + t;
        int pos = f >> 6;
        int c4  = f & 63;
        float4 v = *(const float4*)(ot + pos * OSTR + c4 * 4);
        float s = scl[pos];
        v.x *= s; v.y *= s; v.z *= s; v.w *= s;
        *(float4*)(og + (size_t)pos * CC + c4 * 4) = v;
    }
}

// ------------------------- launch ------------------------------------
extern "C" void kernel_launch(void* const* d_in, const int* in_sizes, int n_in,
                              void* d_out, int out_size) {
    const float* x     = (const float*)d_in[0];
    const float* W     = (const float*)d_in[1];
    const float* b     = (const float*)d_in[2];
    const float* gamma = (const float*)d_in[3];
    const float* beta  = (const float*)d_in[4];
    const float* mean  = (const float*)d_in[5];
    const float* var   = (const float*)d_in[6];
    float* out = (float*)d_out;

    fold_kernel<<<CC, 128>>>(W, b, gamma, beta, mean, var);

    cudaFuncSetAttribute(caps_kernel,
                         cudaFuncAttributeMaxDynamicSharedMemorySize, SMEM_BYTES);
    dim3 grid(LL / TL, BB);
    caps_kernel<<<grid, 256, SMEM_BYTES>>>(x, out);
}

// round 9
// speedup vs baseline: 1.0836x; 1.0027x over previous
#include <cuda_runtime.h>
#include <cuda_fp16.h>
#include <cstdint>

// ------------------------- problem constants -------------------------
#define CC 256
#define LL 8192
#define BB 32
#define TL 64            // positions per CTA
#define KC 32            // K chunk
#define NCHUNK 8
#define NSTAGE 3

// ------------------------- smem layout (bytes) -----------------------
#define XOFF(s)  ((s) * 4096)       // x fp16: 32 k-rows x 128B (xor-swizzled)
#define SBIAS    12288              // 256 floats
#define SQBUF    13312              // 4 x 64 floats
#define SCALE    14336              // 64 floats
#define SMEM_BYTES 14592

// ------------------------- device scratch ----------------------------
// W' fp16 pairs in exact A-fragment order:
// idx = (((kc*2+ks)*16 + mb)*32 + lane)*4 + reg   (each u32 = 2 fp16, k-pair)
// Read directly by MMA warps via LDG.128 (L1-resident: 128KB total).
__device__ __align__(16) unsigned g_Wf[CC * CC / 2];
__device__ float g_bias[CC];

// ------------------------- helpers -----------------------------------
__device__ __forceinline__ uint32_t smem_u32(const void* p) {
    uint32_t a;
    asm("{ .reg .u64 t; cvta.to.shared.u64 t, %1; cvt.u32.u64 %0, t; }"
        : "=r"(a) : "l"(p));
    return a;
}
__device__ __forceinline__ uint32_t pkh2(float a, float b) {
    __half2 h = __floats2half2_rn(a, b);
    return *reinterpret_cast<uint32_t*>(&h);
}
__device__ __forceinline__ void ldsm_x2t(uint32_t* r, uint32_t addr) {
    asm volatile("ldmatrix.sync.aligned.m8n8.x2.trans.shared.b16 {%0,%1}, [%2];"
                 : "=r"(r[0]), "=r"(r[1]) : "r"(addr));
}
__device__ __forceinline__ void mma_f16(float* d, const uint32_t* a, const uint32_t* b) {
    asm volatile(
        "mma.sync.aligned.m16n8k16.row.col.f32.f16.f16.f32 "
        "{%0,%1,%2,%3}, {%4,%5,%6,%7}, {%8,%9}, {%0,%1,%2,%3};"
        : "+f"(d[0]), "+f"(d[1]), "+f"(d[2]), "+f"(d[3])
        : "r"(a[0]), "r"(a[1]), "r"(a[2]), "r"(a[3]), "r"(b[0]), "r"(b[1]));
}

// ------------------------- prep kernel -------------------------------
// Fold BN into W, convert fp16, emit A-fragment-order image (k-pairs packed).
__global__ void fold_kernel(const float* __restrict__ W, const float* __restrict__ b,
                            const float* __restrict__ gamma, const float* __restrict__ beta,
                            const float* __restrict__ mean, const float* __restrict__ var) {
    int o = blockIdx.x;
    int j = threadIdx.x;          // c pair: c = 2j, 2j+1
    float inv = gamma[o] * rsqrtf(var[o] + 1e-5f);
    int c = 2 * j;
    float w0 = W[o * CC + c] * inv;
    float w1 = W[o * CC + c + 1] * inv;
    int kc = c >> 5;              // 32-chunk
    int ks = (c >> 4) & 1;        // k16 step within chunk
    int kl = c & 15;              // k within 16 (even)
    int mb = o >> 4;
    int lane = (o & 7) * 4 + ((kl >> 1) & 3);
    int reg  = ((o >> 3) & 1) + 2 * (kl >> 3);
    g_Wf[(((kc * 2 + ks) * 16 + mb) * 32 + lane) * 4 + reg] = pkh2(w0, w1);
    if (j == 0) g_bias[o] = b[o] * inv + beta[o] - mean[o] * inv;
}

// ------------------------- main kernel -------------------------------
// 256 threads, 8 warps: wm 0..3 (64 oc), wn 0..1 (32 pos). 2 CTAs/SM.
// Tile 256 oc x 64 pos; K in 8 chunks of 32. W fragments come straight
// from gmem (L1-resident); x via LDG->cvt->STS 3-ring; 1 barrier/chunk.
extern "C" __global__ void __launch_bounds__(256, 2)
caps_kernel(const float* __restrict__ x, float* __restrict__ out) {
    extern __shared__ char smem[];
    const uint32_t sbu = smem_u32(smem);
    const int t    = threadIdx.x;
    const int lane = t & 31;
    const int wid  = t >> 5;
    const int wm   = wid & 3;
    const int wn   = wid >> 2;
    const int m0   = wm * 64;
    const int bb   = blockIdx.y;
    const int l0   = blockIdx.x * TL;

    ((float*)(smem + SBIAS))[t] = g_bias[t];

    const float* xg = x + (size_t)bb * CC * LL + l0;

    float acc[4][4][4];
    #pragma unroll
    for (int i = 0; i < 4; i++)
        #pragma unroll
        for (int j = 0; j < 4; j++)
            #pragma unroll
            for (int q = 0; q < 4; q++) acc[i][j][q] = 0.0f;

    // ---- x: LDG prefetch (regs), then cvt+STS later ----
    const int xk = t >> 3;      // k row 0..31
    const int xp = t & 7;       // 8-pos group
    const uint32_t xsts = (uint32_t)(xk * 128 + ((xp ^ (xk & 7)) << 4));
    float4 xa, xb2;
    auto ldg_x = [&](int kc) {
        const float* s = xg + (size_t)(kc * KC + xk) * LL + xp * 8;
        xa  = __ldg((const float4*)s);
        xb2 = __ldg((const float4*)(s + 4));
    };
    auto stage_x = [&](int st) {
        uint4 u;
        u.x = pkh2(xa.x, xa.y);   u.y = pkh2(xa.z, xa.w);
        u.z = pkh2(xb2.x, xb2.y); u.w = pkh2(xb2.z, xb2.w);
        *(uint4*)(smem + XOFF(st) + xsts) = u;
    };

    // ---- mma over one chunk: A frags via LDG.128 (L1-hit after warmup) ----
    const uint4* Wg0 = (const uint4*)g_Wf;      // 1024 uint4 per chunk
    auto do_mma = [&](int st, int kc) {
        const uint4* Wg = Wg0 + (size_t)kc * 1024 + wm * 4 * 32 + lane;
        const uint32_t Xb = sbu + XOFF(st);
        #pragma unroll
        for (int ks = 0; ks < 2; ks++) {
            uint32_t af[4][4], bf[4][2];
            #pragma unroll
            for (int i = 0; i < 4; i++) {
                uint4 v = __ldg(Wg + (ks * 16 + i) * 32);
                af[i][0] = v.x; af[i][1] = v.y; af[i][2] = v.z; af[i][3] = v.w;
            }
            #pragma unroll
            for (int j = 0; j < 4; j++)
                ldsm_x2t(bf[j], Xb + (uint32_t)((ks * 16 + (lane & 15)) * 128
                                   + (((wn * 4 + j) ^ (lane & 7)) << 4)));
            #pragma unroll
            for (int i = 0; i < 4; i++)
                #pragma unroll
                for (int j = 0; j < 4; j++)
                    mma_f16(acc[i][j], af[i], bf[j]);
        }
    };

    // ---- 3-ring pipeline, ONE barrier per chunk ----
    // Slot safety: mma(k) reads slot k%3 while stage_x(k+2) writes (k+2)%3 —
    // distinct; barrier bounds warp skew to < 1 chunk.
    ldg_x(0); stage_x(0);
    ldg_x(1); stage_x(1);

    for (int k = 0; k < NCHUNK; k++) {
        if (k + 2 < NCHUNK) ldg_x(k + 2);
        __syncthreads();                   // x(k) STS visible to all warps
        do_mma(k % NSTAGE, k);
        if (k + 2 < NCHUNK) stage_x((k + 2) % NSTAGE);
    }

    // ---- epilogue: bias + squash + direct store ----
    const float* sbias = (const float*)(smem + SBIAS);
    const int gid = lane >> 2;     // row-within-16 group
    const int qid = lane & 3;      // position pair
    const int n0  = wn * 32;

    float sqA[4], sqB[4];
    #pragma unroll
    for (int j = 0; j < 4; j++) { sqA[j] = 0.0f; sqB[j] = 0.0f; }

    #pragma unroll
    for (int i = 0; i < 4; i++) {
        int r0 = m0 + i * 16 + gid;
        float b0 = sbias[r0], b1 = sbias[r0 + 8];
        #pragma unroll
        for (int j = 0; j < 4; j++) {
            float y0 = acc[i][j][0] + b0;
            float y1 = acc[i][j][1] + b0;
            float y2 = acc[i][j][2] + b1;
            float y3 = acc[i][j][3] + b1;
            acc[i][j][0] = y0; acc[i][j][1] = y1;
            acc[i][j][2] = y2; acc[i][j][3] = y3;
            sqA[j] += y0 * y0 + y2 * y2;
            sqB[j] += y1 * y1 + y3 * y3;
        }
    }
    #pragma unroll
    for (int j = 0; j < 4; j++) {
        #pragma unroll
        for (int m = 4; m < 32; m <<= 1) {
            sqA[j] += __shfl_xor_sync(0xffffffffu, sqA[j], m);
            sqB[j] += __shfl_xor_sync(0xffffffffu, sqB[j], m);
        }
    }
    float* sqb = (float*)(smem + SQBUF);
    if (lane < 4) {
        #pragma unroll
        for (int j = 0; j < 4; j++) {
            int col = n0 + j * 8 + lane * 2;
            sqb[wm * 64 + col]     = sqA[j];
            sqb[wm * 64 + col + 1] = sqB[j];
        }
    }
    __syncthreads();
    if (t < 64) {
        float s = sqb[t] + sqb[64 + t] + sqb[128 + t] + sqb[192 + t];
        float n = sqrtf(s);
        ((float*)(smem + SCALE))[t] = s / ((1.0f + s) * (n + 1e-8f));
    }
    __syncthreads();

    const float* scl = (const float*)(smem + SCALE);
    float* og = out + ((size_t)bb * LL + l0) * CC;
    #pragma unroll
    for (int j = 0; j < 4; j++) {
        int c0 = n0 + j * 8 + qid * 2;       // position
        float s0 = scl[c0], s1 = scl[c0 + 1];
        float* p0 = og + (size_t)c0 * CC;
        float* p1 = og + (size_t)(c0 + 1) * CC;
        #pragma unroll
        for (int i = 0; i < 4; i++) {
            int r0 = m0 + i * 16 + gid;      // channel
            p0[r0]     = acc[i][j][0] * s0;
            p1[r0]     = acc[i][j][1] * s1;
            p0[r0 + 8] = acc[i][j][2] * s0;
            p1[r0 + 8] = acc[i][j][3] * s1;
        }
    }
}

// ------------------------- launch ------------------------------------
extern "C" void kernel_launch(void* const* d_in, const int* in_sizes, int n_in,
                              void* d_out, int out_size) {
    const float* x     = (const float*)d_in[0];
    const float* W     = (const float*)d_in[1];
    const float* b     = (const float*)d_in[2];
    const float* gamma = (const float*)d_in[3];
    const float* beta  = (const float*)d_in[4];
    const float* mean  = (const float*)d_in[5];
    const float* var   = (const float*)d_in[6];
    float* out = (float*)d_out;

    fold_kernel<<<CC, 128>>>(W, b, gamma, beta, mean, var);

    cudaFuncSetAttribute(caps_kernel,
                         cudaFuncAttributeMaxDynamicSharedMemorySize, SMEM_BYTES);
    dim3 grid(LL / TL, BB);
    caps_kernel<<<grid, 256, SMEM_BYTES>>>(x, out);
}